// round 2
// baseline (speedup 1.0000x reference)
#include <cuda_runtime.h>
#include <cfloat>
#include <math.h>

#define CC   64
#define NP   9216      // 96*96 pixels / nodes
#define HS   24        // hsi spatial
#define KNN  5
#define NKNN (NP*KNN)  // 46080 knn edges
#define NEDG (NKNN+NP) // + self loops = 55296

typedef unsigned long long ull;

// ------------------------- scratch (no alloc allowed) -----------------------
__device__ float g_hsi_up[CC*NP];   // [c][pix], also residual
__device__ float g_hfeat[NP*CC];    // [pix][c]
__device__ float g_mfeat[NP*CC];
__device__ float g_z[NP*CC];        // [node][c]
__device__ float g_numer[NP*CC];    // [node][c]
__device__ float g_fmap[CC*NP];     // [c][pix]
__device__ float g_up1[CC*NP];
__device__ float g_el[NP], g_er[NP], g_den[NP];
__device__ unsigned g_mx[NP];
__device__ int g_topk[NP*KNN];

// ------------------------------- helpers ------------------------------------
__device__ __forceinline__ unsigned fenc(float v) {
    unsigned u = __float_as_uint(v);
    return (u & 0x80000000u) ? ~u : (u | 0x80000000u);
}
__device__ __forceinline__ float fdec(unsigned e) {
    unsigned u = (e & 0x80000000u) ? (e ^ 0x80000000u) : ~e;
    return __uint_as_float(u);
}
__device__ __forceinline__ ull pk2(float a, float b) {
    union { ull u; float f[2]; } w; w.f[0]=a; w.f[1]=b; return w.u;
}
__device__ __forceinline__ void upk2(ull v, float &a, float &b) {
    union { ull u; float f[2]; } w; w.u=v; a=w.f[0]; b=w.f[1];
}
__device__ __forceinline__ ull fma2(ull a, ull b, ull c) {
#if defined(__CUDA_ARCH__) && __CUDA_ARCH__ >= 1000
    ull d;
    asm("fma.rn.f32x2 %0, %1, %2, %3;" : "=l"(d) : "l"(a), "l"(b), "l"(c));
    return d;
#else
    union { ull u; float f[2]; } wa, wb, wc;
    wa.u=a; wb.u=b; wc.u=c;
    wc.f[0]=fmaf(wa.f[0],wb.f[0],wc.f[0]);
    wc.f[1]=fmaf(wa.f[1],wb.f[1],wc.f[1]);
    return wc.u;
#endif
}

// bicubic weights (torch a=-0.75, align_corners=False, border replicate)
__device__ __forceinline__ void bicw(int o, float *w, int *id, int n) {
    float x = (o + 0.5f) * 0.25f - 0.5f;
    float fi = floorf(x);
    int   i0 = (int)fi;
    float t  = x - fi;
#pragma unroll
    for (int k = 0; k < 4; ++k) {
        int off = k - 1;
        float d = fabsf(t - (float)off);
        float wv;
        if (d <= 1.f)      wv = (1.25f * d - 2.25f) * d * d + 1.f;
        else if (d < 2.f)  wv = ((-0.75f * d + 3.75f) * d - 6.f) * d + 3.f;
        else               wv = 0.f;
        int ii = i0 + off;
        ii = ii < 0 ? 0 : (ii > n - 1 ? n - 1 : ii);
        id[k] = ii; w[k] = wv;
    }
}

// ---------------- K1: bicubic x4 upsample hsi -> g_hsi_up -------------------
__global__ __launch_bounds__(256) void k_bicubic(const float *__restrict__ hsi) {
    int i = blockIdx.x * 256 + threadIdx.x;
    if (i >= CC * NP) return;
    int c = i / NP, p = i % NP, oy = p / 96, ox = p % 96;
    float wy[4], wx[4]; int iy[4], ix[4];
    bicw(oy, wy, iy, HS);
    bicw(ox, wx, ix, HS);
    const float *s = hsi + c * (HS * HS);
    float acc = 0.f;
#pragma unroll
    for (int a = 0; a < 4; ++a) {
        float r = 0.f;
#pragma unroll
        for (int b = 0; b < 4; ++b) r += wx[b] * s[iy[a] * HS + ix[b]];
        acc += wy[a] * r;
    }
    g_hsi_up[i] = acc;
}

// ---------------- K2: embed (2x conv1x1 + PReLU) ----------------------------
// flag==0: in = g_hsi_up, out = g_hfeat;  flag==1: in = msi arg, out = g_mfeat
__global__ __launch_bounds__(256) void k_embed(
    const float *__restrict__ msi, int flag,
    const float *__restrict__ Wa, const float *__restrict__ ba, const float *__restrict__ aa,
    const float *__restrict__ Wb, const float *__restrict__ bb, const float *__restrict__ ab)
{
    __shared__ float sWa[64*65], sWb[64*65], sx[16*65], smid[16*65];
    const float *in = flag ? msi : (const float*)g_hsi_up;
    float *feat = flag ? g_mfeat : g_hfeat;
    int tid = threadIdx.x;
    for (int i = tid; i < 4096; i += 256) {
        int o = i >> 6, c = i & 63;
        sWa[o*65+c] = Wa[i]; sWb[o*65+c] = Wb[i];
    }
    int pix0 = blockIdx.x * 16;
    for (int i = tid; i < 1024; i += 256) {
        int c = i >> 4, p = i & 15;
        sx[p*65+c] = in[c*NP + pix0 + p];
    }
    float A1 = aa[0], A2 = ab[0];
    int oc = tid & 63, pg = tid >> 6;
    float bA = ba[oc], bB = bb[oc];
    __syncthreads();
    float acc[4];
#pragma unroll
    for (int j = 0; j < 4; ++j) acc[j] = bA;
#pragma unroll 8
    for (int ic = 0; ic < 64; ++ic) {
        float w = sWa[oc*65+ic];
#pragma unroll
        for (int j = 0; j < 4; ++j) acc[j] += w * sx[(4*pg+j)*65+ic];
    }
#pragma unroll
    for (int j = 0; j < 4; ++j) {
        float v = acc[j]; v = v >= 0.f ? v : A1 * v;
        smid[(4*pg+j)*65+oc] = v;
    }
    __syncthreads();
#pragma unroll
    for (int j = 0; j < 4; ++j) acc[j] = bB;
#pragma unroll 8
    for (int ic = 0; ic < 64; ++ic) {
        float w = sWb[oc*65+ic];
#pragma unroll
        for (int j = 0; j < 4; ++j) acc[j] += w * smid[(4*pg+j)*65+ic];
    }
#pragma unroll
    for (int j = 0; j < 4; ++j) {
        float v = acc[j]; v = v >= 0.f ? v : A2 * v;
        feat[(pix0 + 4*pg + j)*64 + oc] = v;
    }
}

// --------- K3: fused sim GEMM (9216x9216x64) + exact per-row top-5 ----------
// CTA: 256 thr (16x16), 64 rows, scans all 9216 cols in chunks of 96.
__global__ __launch_bounds__(256) void k_sim()
{
    __shared__ float pool[4160 + 6272];   // sA[64][65] | sB[64][98]; reused for merge
    float *sA = pool;
    float *sB = pool + 4160;
    int tid = threadIdx.x, tx = tid & 15, ty = tid >> 4;
    int row0 = blockIdx.x * 64;
    for (int i = tid; i < 4096; i += 256) {
        int r = i >> 6, k = i & 63;
        sA[r*65+k] = g_hfeat[(row0 + r)*64 + k];
    }
    float tv[4][5]; int ti[4][5];
#pragma unroll
    for (int i = 0; i < 4; ++i)
#pragma unroll
        for (int s = 0; s < 5; ++s) { tv[i][s] = -FLT_MAX; ti[i][s] = 0x7fffffff; }
    ull acc[4][3];
    int r0 = ty * 4, c0 = tx * 6;
    for (int cb = 0; cb < NP; cb += 96) {
        __syncthreads();
        for (int i = tid; i < 6144; i += 256) {
            int col = i >> 6, k = i & 63;
            sB[k*98 + col] = g_mfeat[(cb + col)*64 + k];
        }
        __syncthreads();
#pragma unroll
        for (int i = 0; i < 4; ++i)
#pragma unroll
            for (int j = 0; j < 3; ++j) acc[i][j] = pk2(0.f, 0.f);
#pragma unroll 4
        for (int k = 0; k < 64; ++k) {
            ull b0 = *(const ull*)&sB[k*98 + c0];
            ull b1 = *(const ull*)&sB[k*98 + c0 + 2];
            ull b2 = *(const ull*)&sB[k*98 + c0 + 4];
#pragma unroll
            for (int i = 0; i < 4; ++i) {
                float a = sA[(r0+i)*65 + k];
                ull aa2 = pk2(a, a);
                acc[i][0] = fma2(aa2, b0, acc[i][0]);
                acc[i][1] = fma2(aa2, b1, acc[i][1]);
                acc[i][2] = fma2(aa2, b2, acc[i][2]);
            }
        }
        // update per-thread running top-5 (cols processed in ascending order)
#pragma unroll
        for (int i = 0; i < 4; ++i) {
#pragma unroll
            for (int j = 0; j < 3; ++j) {
                float v0, v1; upk2(acc[i][j], v0, v1);
                int cA = cb + c0 + 2*j;
                if (v0 > tv[i][4]) {
                    tv[i][4] = v0; ti[i][4] = cA;
#pragma unroll
                    for (int s = 4; s >= 1; --s)
                        if (tv[i][s] > tv[i][s-1]) {
                            float t = tv[i][s]; tv[i][s] = tv[i][s-1]; tv[i][s-1] = t;
                            int u = ti[i][s]; ti[i][s] = ti[i][s-1]; ti[i][s-1] = u;
                        }
                }
                if (v1 > tv[i][4]) {
                    tv[i][4] = v1; ti[i][4] = cA + 1;
#pragma unroll
                    for (int s = 4; s >= 1; --s)
                        if (tv[i][s] > tv[i][s-1]) {
                            float t = tv[i][s]; tv[i][s] = tv[i][s-1]; tv[i][s-1] = t;
                            int u = ti[i][s]; ti[i][s] = ti[i][s-1]; ti[i][s-1] = u;
                        }
                }
            }
        }
    }
    __syncthreads();
    // merge 16 partial top-5 lists per row (tie-break: value desc, index asc)
    float *mval = pool;               // [64][80]
    int   *midx = (int*)(pool + 5120);
#pragma unroll
    for (int i = 0; i < 4; ++i)
#pragma unroll
        for (int s = 0; s < 5; ++s) {
            mval[(r0+i)*80 + tx*5 + s] = tv[i][s];
            midx[(r0+i)*80 + tx*5 + s] = ti[i][s];
        }
    __syncthreads();
    if (tid < 64) {
        float bv[5]; int bi[5];
#pragma unroll
        for (int s = 0; s < 5; ++s) { bv[s] = -FLT_MAX; bi[s] = 0x7fffffff; }
        for (int q = 0; q < 80; ++q) {
            float v = mval[tid*80 + q]; int ix = midx[tid*80 + q];
            if (v > bv[4] || (v == bv[4] && ix < bi[4])) {
                bv[4] = v; bi[4] = ix;
#pragma unroll
                for (int s = 4; s >= 1; --s)
                    if (bv[s] > bv[s-1] || (bv[s] == bv[s-1] && bi[s] < bi[s-1])) {
                        float t = bv[s]; bv[s] = bv[s-1]; bv[s-1] = t;
                        int u = bi[s]; bi[s] = bi[s-1]; bi[s-1] = u;
                    }
            }
        }
#pragma unroll
        for (int s = 0; s < 5; ++s) g_topk[(row0 + tid)*5 + s] = bi[s];
    }
}

// ---------------- K4: z = [hfeat|mfeat] @ Wg --------------------------------
__global__ __launch_bounds__(256) void k_z(const float *__restrict__ Wg)
{
    __shared__ float sWg[128*64];       // natural [ic][oc] layout, conflict-free
    __shared__ float sx[16*130];
    int tid = threadIdx.x;
    for (int i = tid; i < 8192; i += 256) sWg[i] = Wg[i];
    int n0 = blockIdx.x * 16;
    for (int i = tid; i < 2048; i += 256) {
        int p = i >> 7, c = i & 127;
        float v = c < 64 ? g_hfeat[(n0+p)*64 + c] : g_mfeat[(n0+p)*64 + (c-64)];
        sx[p*130 + c] = v;
    }
    __syncthreads();
    int oc = tid & 63, pg = tid >> 6;
    float acc[4] = {0.f, 0.f, 0.f, 0.f};
#pragma unroll 8
    for (int ic = 0; ic < 128; ++ic) {
        float w = sWg[ic*64 + oc];
#pragma unroll
        for (int j = 0; j < 4; ++j) acc[j] += w * sx[(4*pg+j)*130 + ic];
    }
#pragma unroll
    for (int j = 0; j < 4; ++j) g_z[(n0 + 4*pg + j)*64 + oc] = acc[j];
}

// ---------------- K5: el/er per-node attention scores -----------------------
__global__ __launch_bounds__(256) void k_elr(const float *__restrict__ al,
                                             const float *__restrict__ ar)
{
    int wid = (blockIdx.x * 256 + threadIdx.x) >> 5;
    int lane = threadIdx.x & 31;
    if (wid >= NP) return;
    float z0 = g_z[wid*64 + lane], z1 = g_z[wid*64 + lane + 32];
    float tl = z0 * al[lane] + z1 * al[lane + 32];
    float tr = z0 * ar[lane] + z1 * ar[lane + 32];
#pragma unroll
    for (int o = 16; o > 0; o >>= 1) {
        tl += __shfl_down_sync(0xffffffffu, tl, o);
        tr += __shfl_down_sync(0xffffffffu, tr, o);
    }
    if (lane == 0) { g_el[wid] = tl; g_er[wid] = tr; }
}

// ---------------- K6: GAT edge softmax + aggregation ------------------------
__global__ __launch_bounds__(256) void k_gat_init()
{
    int i = blockIdx.x * 256 + threadIdx.x;
    if (i < NP*CC) g_numer[i] = 0.f;
    if (i < NP) { g_den[i] = 0.f; g_mx[i] = 0u; }
}

__global__ __launch_bounds__(256) void k_gat_max()
{
    int e = blockIdx.x * 256 + threadIdx.x;
    if (e >= NEDG) return;
    int s, d;
    if (e < NKNN) { s = e % NP; d = g_topk[e]; }
    else          { s = d = e - NKNN; }
    float x = g_el[s] + g_er[d];
    float lg = x >= 0.f ? x : 0.2f * x;
    atomicMax(&g_mx[d], fenc(lg));
}

__global__ __launch_bounds__(256) void k_gat_acc()
{
    int e = (blockIdx.x * 256 + threadIdx.x) >> 5;
    int lane = threadIdx.x & 31;
    if (e >= NEDG) return;
    int s, d;
    if (e < NKNN) { s = e % NP; d = g_topk[e]; }
    else          { s = d = e - NKNN; }
    float x = g_el[s] + g_er[d];
    float lg = x >= 0.f ? x : 0.2f * x;
    float ex = __expf(lg - fdec(g_mx[d]));
    if (lane == 0) atomicAdd(&g_den[d], ex);
    atomicAdd(&g_numer[d*64 + lane],      ex * g_z[s*64 + lane]);
    atomicAdd(&g_numer[d*64 + lane + 32], ex * g_z[s*64 + lane + 32]);
}

__global__ __launch_bounds__(256) void k_gat_fin(const float *__restrict__ bg)
{
    int i = blockIdx.x * 256 + threadIdx.x;
    if (i >= CC*NP) return;
    int c = i / NP, n = i % NP;
    g_fmap[i] = g_numer[n*64 + c] / g_den[n] + bg[c];
}

// ---------------- K7: conv3x3 + bias + PReLU (+ residual) -------------------
// sel==0: g_fmap -> g_up1;  sel==1: g_up1 -> d_out (+= g_hsi_up)
__global__ __launch_bounds__(256) void k_conv(
    const float *__restrict__ Kw, const float *__restrict__ bias,
    const float *__restrict__ alpha, float *__restrict__ dout, int sel)
{
    __shared__ float in_s[8*18*22];     // [ic8][yy18][xx22] (pad 22: conflict-free LDS.64)
    __shared__ float w_s[16*8*9];       // [oc16][ic8][tap9]
    const float *in = sel ? (const float*)g_up1 : (const float*)g_fmap;
    float *out = sel ? dout : (float*)g_up1;
    int tid = threadIdx.x;
    int b = blockIdx.x;
    int x0 = (b % 6) * 16, y0 = ((b / 6) % 6) * 16, ocb = (b / 36) * 16;
    int oc = tid >> 4, g = tid & 15;
    ull acc2[8];
#pragma unroll
    for (int m = 0; m < 8; ++m) acc2[m] = pk2(0.f, 0.f);
    for (int ic0 = 0; ic0 < 64; ic0 += 8) {
        __syncthreads();
        for (int i = tid; i < 2592; i += 256) {
            int ii = i / 324, rem = i % 324, yy = rem / 18, xx = rem % 18;
            int y = y0 + yy - 1, x = x0 + xx - 1;
            float v = (y >= 0 && y < 96 && x >= 0 && x < 96) ? in[(ic0+ii)*NP + y*96 + x] : 0.f;
            in_s[ii*396 + yy*22 + xx] = v;
        }
        for (int i = tid; i < 1152; i += 256) {
            int o = i / 72, rem = i % 72;
            w_s[i] = Kw[(ocb + o)*576 + ic0*9 + rem];
        }
        __syncthreads();
#pragma unroll
        for (int ic = 0; ic < 8; ++ic) {
#pragma unroll
            for (int dy = 0; dy < 3; ++dy) {
                const float *row = &in_s[ic*396 + (g + dy)*22];
                ull P[9];
#pragma unroll
                for (int m = 0; m < 9; ++m) P[m] = *(const ull*)&row[2*m];
                ull O[8];
#pragma unroll
                for (int m = 0; m < 8; ++m) {
                    float lo, hi, lo2, hi2;
                    upk2(P[m], lo, hi); upk2(P[m+1], lo2, hi2);
                    O[m] = pk2(hi, lo2);
                }
                const float *wr = &w_s[oc*72 + ic*9 + dy*3];
                ull w0 = pk2(wr[0], wr[0]);
                ull w1 = pk2(wr[1], wr[1]);
                ull w2 = pk2(wr[2], wr[2]);
#pragma unroll
                for (int m = 0; m < 8; ++m) {
                    acc2[m] = fma2(w0, P[m],   acc2[m]);
                    acc2[m] = fma2(w1, O[m],   acc2[m]);
                    acc2[m] = fma2(w2, P[m+1], acc2[m]);
                }
            }
        }
    }
    float bv = bias[ocb + oc], av = alpha[0];
    int ocg = ocb + oc;
#pragma unroll
    for (int m = 0; m < 8; ++m) {
        float v0, v1; upk2(acc2[m], v0, v1);
        v0 += bv; v1 += bv;
        v0 = v0 >= 0.f ? v0 : av * v0;
        v1 = v1 >= 0.f ? v1 : av * v1;
        int o = ocg*NP + (y0 + g)*96 + x0 + 2*m;
        if (sel) { v0 += g_hsi_up[o]; v1 += g_hsi_up[o+1]; }
        out[o] = v0; out[o+1] = v1;
    }
}

// ---------------------------------------------------------------------------
extern "C" void kernel_launch(void* const* d_in, const int* in_sizes, int n_in,
                              void* d_out, int out_size)
{
    const float *msi = (const float*)d_in[0];
    const float *hsi = (const float*)d_in[1];
    const float *W1a = (const float*)d_in[2],  *b1a = (const float*)d_in[3],  *a1a = (const float*)d_in[4];
    const float *W1b = (const float*)d_in[5],  *b1b = (const float*)d_in[6],  *a1b = (const float*)d_in[7];
    const float *W2a = (const float*)d_in[8],  *b2a = (const float*)d_in[9],  *a2a = (const float*)d_in[10];
    const float *W2b = (const float*)d_in[11], *b2b = (const float*)d_in[12], *a2b = (const float*)d_in[13];
    const float *Wg  = (const float*)d_in[14];
    const float *al  = (const float*)d_in[15], *ar = (const float*)d_in[16], *bg = (const float*)d_in[17];
    const float *Ku1 = (const float*)d_in[18], *bu1 = (const float*)d_in[19], *au1 = (const float*)d_in[20];
    const float *Ku2 = (const float*)d_in[21], *bu2 = (const float*)d_in[22], *au2 = (const float*)d_in[23];
    float *out = (float*)d_out;

    k_bicubic<<<2304, 256>>>(hsi);
    k_embed<<<576, 256>>>(msi, 0, W1a, b1a, a1a, W1b, b1b, a1b);   // hsi branch
    k_embed<<<576, 256>>>(msi, 1, W2a, b2a, a2a, W2b, b2b, a2b);   // msi branch
    k_sim<<<144, 256>>>();
    k_z<<<576, 256>>>(Wg);
    k_elr<<<1152, 256>>>(al, ar);
    k_gat_init<<<2304, 256>>>();
    k_gat_max<<<216, 256>>>();
    k_gat_acc<<<6912, 256>>>();
    k_gat_fin<<<2304, 256>>>(bg);
    k_conv<<<144, 256>>>(Ku1, bu1, au1, out, 0);
    k_conv<<<144, 256>>>(Ku2, bu2, au2, out, 1);
}

// round 5
// speedup vs baseline: 1.2598x; 1.2598x over previous
#include <cuda_runtime.h>
#include <cfloat>
#include <math.h>

#define CC   64
#define NP   9216      // 96*96 pixels / nodes
#define HS   24        // hsi spatial
#define KNN  5
#define NKNN (NP*KNN)  // 46080 knn edges
#define NEDG (NKNN+NP) // + self loops = 55296

typedef unsigned long long ull;

// ------------------------- scratch (no alloc allowed) -----------------------
__device__ float g_hsi_up[CC*NP];   // [c][pix], also residual
__device__ float g_hfeat[NP*CC];    // [pix][c]
__device__ float g_mfeat[NP*CC];
__device__ float g_z[NP*CC];        // [node][c]
__device__ float g_numer[NP*CC];    // [node][c]
__device__ float g_fmap[CC*NP];     // [c][pix]
__device__ float g_up1[CC*NP];
__device__ float g_el[NP], g_er[NP], g_den[NP];
__device__ unsigned g_mx[NP];
__device__ int g_topk[NP*KNN];
__device__ float g_tvp[2*NP*KNN];   // partial top-5 values (per column half)
__device__ int   g_tip[2*NP*KNN];   // partial top-5 indices

// ------------------------------- helpers ------------------------------------
__device__ __forceinline__ unsigned fenc(float v) {
    unsigned u = __float_as_uint(v);
    return (u & 0x80000000u) ? ~u : (u | 0x80000000u);
}
__device__ __forceinline__ float fdec(unsigned e) {
    unsigned u = (e & 0x80000000u) ? (e ^ 0x80000000u) : ~e;
    return __uint_as_float(u);
}
__device__ __forceinline__ ull pk2(float a, float b) {
    ull d;
    asm("mov.b64 %0, {%1, %2};" : "=l"(d) : "f"(a), "f"(b));
    return d;
}
__device__ __forceinline__ ull dup2(float a) {
    ull d;
    asm("mov.b64 %0, {%1, %1};" : "=l"(d) : "f"(a));
    return d;
}
__device__ __forceinline__ void upk2(ull v, float &a, float &b) {
    asm("mov.b64 {%0, %1}, %2;" : "=f"(a), "=f"(b) : "l"(v));
}
__device__ __forceinline__ ull fma2(ull a, ull b, ull c) {
    ull d;
    asm("fma.rn.f32x2 %0, %1, %2, %3;" : "=l"(d) : "l"(a), "l"(b), "l"(c));
    return d;
}

// bicubic weights (torch a=-0.75, align_corners=False, border replicate)
__device__ __forceinline__ void bicw(int o, float *w, int *id, int n) {
    float x = (o + 0.5f) * 0.25f - 0.5f;
    float fi = floorf(x);
    int   i0 = (int)fi;
    float t  = x - fi;
#pragma unroll
    for (int k = 0; k < 4; ++k) {
        int off = k - 1;
        float d = fabsf(t - (float)off);
        float wv;
        if (d <= 1.f)      wv = (1.25f * d - 2.25f) * d * d + 1.f;
        else if (d < 2.f)  wv = ((-0.75f * d + 3.75f) * d - 6.f) * d + 3.f;
        else               wv = 0.f;
        int ii = i0 + off;
        ii = ii < 0 ? 0 : (ii > n - 1 ? n - 1 : ii);
        id[k] = ii; w[k] = wv;
    }
}

// ---------------- K1: bicubic x4 upsample hsi -> g_hsi_up -------------------
__global__ __launch_bounds__(256) void k_bicubic(const float *__restrict__ hsi) {
    int i = blockIdx.x * 256 + threadIdx.x;
    if (i >= CC * NP) return;
    int c = i / NP, p = i % NP, oy = p / 96, ox = p % 96;
    float wy[4], wx[4]; int iy[4], ix[4];
    bicw(oy, wy, iy, HS);
    bicw(ox, wx, ix, HS);
    const float *s = hsi + c * (HS * HS);
    float acc = 0.f;
#pragma unroll
    for (int a = 0; a < 4; ++a) {
        float r = 0.f;
#pragma unroll
        for (int b = 0; b < 4; ++b) r += wx[b] * s[iy[a] * HS + ix[b]];
        acc += wy[a] * r;
    }
    g_hsi_up[i] = acc;
}

// ---------------- K2: embed (2x conv1x1 + PReLU) ----------------------------
__global__ __launch_bounds__(256) void k_embed(
    const float *__restrict__ msi, int flag,
    const float *__restrict__ Wa, const float *__restrict__ ba, const float *__restrict__ aa,
    const float *__restrict__ Wb, const float *__restrict__ bb, const float *__restrict__ ab)
{
    __shared__ float sWa[64*65], sWb[64*65], sx[16*65], smid[16*65];
    const float *in = flag ? msi : (const float*)g_hsi_up;
    float *feat = flag ? g_mfeat : g_hfeat;
    int tid = threadIdx.x;
    for (int i = tid; i < 4096; i += 256) {
        int o = i >> 6, c = i & 63;
        sWa[o*65+c] = Wa[i]; sWb[o*65+c] = Wb[i];
    }
    int pix0 = blockIdx.x * 16;
    for (int i = tid; i < 1024; i += 256) {
        int c = i >> 4, p = i & 15;
        sx[p*65+c] = in[c*NP + pix0 + p];
    }
    float A1 = aa[0], A2 = ab[0];
    int oc = tid & 63, pg = tid >> 6;
    float bA = ba[oc], bB = bb[oc];
    __syncthreads();
    float acc[4];
#pragma unroll
    for (int j = 0; j < 4; ++j) acc[j] = bA;
#pragma unroll 8
    for (int ic = 0; ic < 64; ++ic) {
        float w = sWa[oc*65+ic];
#pragma unroll
        for (int j = 0; j < 4; ++j) acc[j] += w * sx[(4*pg+j)*65+ic];
    }
#pragma unroll
    for (int j = 0; j < 4; ++j) {
        float v = acc[j]; v = v >= 0.f ? v : A1 * v;
        smid[(4*pg+j)*65+oc] = v;
    }
    __syncthreads();
#pragma unroll
    for (int j = 0; j < 4; ++j) acc[j] = bB;
#pragma unroll 8
    for (int ic = 0; ic < 64; ++ic) {
        float w = sWb[oc*65+ic];
#pragma unroll
        for (int j = 0; j < 4; ++j) acc[j] += w * smid[(4*pg+j)*65+ic];
    }
#pragma unroll
    for (int j = 0; j < 4; ++j) {
        float v = acc[j]; v = v >= 0.f ? v : A2 * v;
        feat[(pix0 + 4*pg + j)*64 + oc] = v;
    }
}

// --------- K3: fused sim GEMM + exact per-row top-5, column-split x2 --------
// grid = 288: blockIdx>>1 = row tile (64 rows), blockIdx&1 = column half (4608).
// 256 thr (16x16); thread tile 4 rows x 6 cols; sA k-major for LDS.128 A loads.
__global__ __launch_bounds__(256, 2) void k_sim()
{
    __shared__ float sA[64*80];       // [k][80]: rows (20480 B)
    __shared__ float sB[64*98];       // [k][98]: cols (25088 B)
    int tid = threadIdx.x, tx = tid & 15, ty = tid >> 4;
    int row0 = (blockIdx.x >> 1) * 64;
    int half = blockIdx.x & 1;
    int cbase = half * (NP/2);
    for (int i = tid; i < 4096; i += 256) {
        int r = i >> 6, k = i & 63;
        sA[k*80 + r] = g_hfeat[(row0 + r)*64 + k];
    }
    float tv[4][5]; int ti[4][5];
#pragma unroll
    for (int i = 0; i < 4; ++i)
#pragma unroll
        for (int s = 0; s < 5; ++s) { tv[i][s] = -FLT_MAX; ti[i][s] = 0x7fffffff; }
    int r0 = ty * 4, c0 = tx * 6;
    for (int cb = cbase; cb < cbase + NP/2; cb += 96) {
        __syncthreads();
        for (int i = tid; i < 6144; i += 256) {
            int col = i >> 6, k = i & 63;
            sB[k*98 + col] = g_mfeat[(cb + col)*64 + k];
        }
        __syncthreads();
        ull acc[2][6];
#pragma unroll
        for (int p = 0; p < 2; ++p)
#pragma unroll
            for (int c = 0; c < 6; ++c) acc[p][c] = 0ull;
#pragma unroll 8
        for (int k = 0; k < 64; ++k) {
            float4 av = *(const float4*)&sA[k*80 + r0];
            float2 b01 = *(const float2*)&sB[k*98 + c0];
            float2 b23 = *(const float2*)&sB[k*98 + c0 + 2];
            float2 b45 = *(const float2*)&sB[k*98 + c0 + 4];
            ull a01 = pk2(av.x, av.y);
            ull a23 = pk2(av.z, av.w);
            ull B0 = dup2(b01.x), B1 = dup2(b01.y);
            ull B2 = dup2(b23.x), B3 = dup2(b23.y);
            ull B4 = dup2(b45.x), B5 = dup2(b45.y);
            acc[0][0] = fma2(a01, B0, acc[0][0]);
            acc[0][1] = fma2(a01, B1, acc[0][1]);
            acc[0][2] = fma2(a01, B2, acc[0][2]);
            acc[0][3] = fma2(a01, B3, acc[0][3]);
            acc[0][4] = fma2(a01, B4, acc[0][4]);
            acc[0][5] = fma2(a01, B5, acc[0][5]);
            acc[1][0] = fma2(a23, B0, acc[1][0]);
            acc[1][1] = fma2(a23, B1, acc[1][1]);
            acc[1][2] = fma2(a23, B2, acc[1][2]);
            acc[1][3] = fma2(a23, B3, acc[1][3]);
            acc[1][4] = fma2(a23, B4, acc[1][4]);
            acc[1][5] = fma2(a23, B5, acc[1][5]);
        }
        // fold chunk results into running per-row top-5 (ascending col order)
#pragma unroll
        for (int p = 0; p < 2; ++p) {
#pragma unroll
            for (int c = 0; c < 6; ++c) {
                float vlo, vhi; upk2(acc[p][c], vlo, vhi);
                int col = cb + c0 + c;
                int rlo = 2*p, rhi = 2*p + 1;
                if (vlo > tv[rlo][4]) {
                    tv[rlo][4] = vlo; ti[rlo][4] = col;
#pragma unroll
                    for (int s = 4; s >= 1; --s)
                        if (tv[rlo][s] > tv[rlo][s-1]) {
                            float t = tv[rlo][s]; tv[rlo][s] = tv[rlo][s-1]; tv[rlo][s-1] = t;
                            int u = ti[rlo][s]; ti[rlo][s] = ti[rlo][s-1]; ti[rlo][s-1] = u;
                        }
                }
                if (vhi > tv[rhi][4]) {
                    tv[rhi][4] = vhi; ti[rhi][4] = col;
#pragma unroll
                    for (int s = 4; s >= 1; --s)
                        if (tv[rhi][s] > tv[rhi][s-1]) {
                            float t = tv[rhi][s]; tv[rhi][s] = tv[rhi][s-1]; tv[rhi][s-1] = t;
                            int u = ti[rhi][s]; ti[rhi][s] = ti[rhi][s-1]; ti[rhi][s-1] = u;
                        }
                }
            }
        }
    }
    __syncthreads();
    // merge 16 partial top-5 lists per row (tie-break: value desc, index asc)
    float *mval = sB;                  // 64 rows x 80 entries
    int   *midx = (int*)sA;
#pragma unroll
    for (int i = 0; i < 4; ++i)
#pragma unroll
        for (int s = 0; s < 5; ++s) {
            mval[(r0+i)*80 + tx*5 + s] = tv[i][s];
            midx[(r0+i)*80 + tx*5 + s] = ti[i][s];
        }
    __syncthreads();
    if (tid < 64) {
        float bv[5]; int bi[5];
#pragma unroll
        for (int s = 0; s < 5; ++s) { bv[s] = -FLT_MAX; bi[s] = 0x7fffffff; }
        for (int q = 0; q < 80; ++q) {
            float v = mval[tid*80 + q]; int ix = midx[tid*80 + q];
            if (v > bv[4] || (v == bv[4] && ix < bi[4])) {
                bv[4] = v; bi[4] = ix;
#pragma unroll
                for (int s = 4; s >= 1; --s)
                    if (bv[s] > bv[s-1] || (bv[s] == bv[s-1] && bi[s] < bi[s-1])) {
                        float t = bv[s]; bv[s] = bv[s-1]; bv[s-1] = t;
                        int u = bi[s]; bi[s] = bi[s-1]; bi[s-1] = u;
                    }
            }
        }
        int base = half*NP*KNN + (row0 + tid)*KNN;
#pragma unroll
        for (int s = 0; s < 5; ++s) { g_tvp[base + s] = bv[s]; g_tip[base + s] = bi[s]; }
    }
}

// ---------------- K3b: merge the two column-half top-5 lists ----------------
__global__ __launch_bounds__(256) void k_topk_merge()
{
    int row = blockIdx.x * 256 + threadIdx.x;
    if (row >= NP) return;
    float v0[5], v1[5]; int i0[5], i1[5];
#pragma unroll
    for (int s = 0; s < 5; ++s) {
        v0[s] = g_tvp[row*KNN + s];          i0[s] = g_tip[row*KNN + s];
        v1[s] = g_tvp[NP*KNN + row*KNN + s]; i1[s] = g_tip[NP*KNN + row*KNN + s];
    }
    int p0 = 0, p1 = 0;
#pragma unroll
    for (int s = 0; s < 5; ++s) {
        bool take0;
        if (p0 >= 5) take0 = false;
        else if (p1 >= 5) take0 = true;
        else take0 = (v0[p0] > v1[p1]) || (v0[p0] == v1[p1] && i0[p0] < i1[p1]);
        if (take0) { g_topk[row*KNN + s] = i0[p0++]; }
        else       { g_topk[row*KNN + s] = i1[p1++]; }
    }
}

// ---------------- K4: z = [hfeat|mfeat] @ Wg --------------------------------
__global__ __launch_bounds__(256) void k_z(const float *__restrict__ Wg)
{
    __shared__ float sWg[128*64];
    __shared__ float sx[16*130];
    int tid = threadIdx.x;
    for (int i = tid; i < 8192; i += 256) sWg[i] = Wg[i];
    int n0 = blockIdx.x * 16;
    for (int i = tid; i < 2048; i += 256) {
        int p = i >> 7, c = i & 127;
        float v = c < 64 ? g_hfeat[(n0+p)*64 + c] : g_mfeat[(n0+p)*64 + (c-64)];
        sx[p*130 + c] = v;
    }
    __syncthreads();
    int oc = tid & 63, pg = tid >> 6;
    float acc[4] = {0.f, 0.f, 0.f, 0.f};
#pragma unroll 8
    for (int ic = 0; ic < 128; ++ic) {
        float w = sWg[ic*64 + oc];
#pragma unroll
        for (int j = 0; j < 4; ++j) acc[j] += w * sx[(4*pg+j)*130 + ic];
    }
#pragma unroll
    for (int j = 0; j < 4; ++j) g_z[(n0 + 4*pg + j)*64 + oc] = acc[j];
}

// ---------------- K5: el/er per-node attention scores -----------------------
__global__ __launch_bounds__(256) void k_elr(const float *__restrict__ al,
                                             const float *__restrict__ ar)
{
    int wid = (blockIdx.x * 256 + threadIdx.x) >> 5;
    int lane = threadIdx.x & 31;
    if (wid >= NP) return;
    float z0 = g_z[wid*64 + lane], z1 = g_z[wid*64 + lane + 32];
    float tl = z0 * al[lane] + z1 * al[lane + 32];
    float tr = z0 * ar[lane] + z1 * ar[lane + 32];
#pragma unroll
    for (int o = 16; o > 0; o >>= 1) {
        tl += __shfl_down_sync(0xffffffffu, tl, o);
        tr += __shfl_down_sync(0xffffffffu, tr, o);
    }
    if (lane == 0) { g_el[wid] = tl; g_er[wid] = tr; }
}

// ---------------- K6: GAT edge softmax + aggregation ------------------------
__global__ __launch_bounds__(256) void k_gat_init()
{
    int i = blockIdx.x * 256 + threadIdx.x;
    if (i < NP*CC) g_numer[i] = 0.f;
    if (i < NP) { g_den[i] = 0.f; g_mx[i] = 0u; }
}

__global__ __launch_bounds__(256) void k_gat_max()
{
    int e = blockIdx.x * 256 + threadIdx.x;
    if (e >= NEDG) return;
    int s, d;
    if (e < NKNN) { s = e % NP; d = g_topk[e]; }
    else          { s = d = e - NKNN; }
    float x = g_el[s] + g_er[d];
    float lg = x >= 0.f ? x : 0.2f * x;
    atomicMax(&g_mx[d], fenc(lg));
}

__global__ __launch_bounds__(256) void k_gat_acc()
{
    int e = (blockIdx.x * 256 + threadIdx.x) >> 5;
    int lane = threadIdx.x & 31;
    if (e >= NEDG) return;
    int s, d;
    if (e < NKNN) { s = e % NP; d = g_topk[e]; }
    else          { s = d = e - NKNN; }
    float x = g_el[s] + g_er[d];
    float lg = x >= 0.f ? x : 0.2f * x;
    float ex = __expf(lg - fdec(g_mx[d]));
    if (lane == 0) atomicAdd(&g_den[d], ex);
    atomicAdd(&g_numer[d*64 + lane],      ex * g_z[s*64 + lane]);
    atomicAdd(&g_numer[d*64 + lane + 32], ex * g_z[s*64 + lane + 32]);
}

__global__ __launch_bounds__(256) void k_gat_fin(const float *__restrict__ bg)
{
    int i = blockIdx.x * 256 + threadIdx.x;
    if (i >= CC*NP) return;
    int c = i / NP, n = i % NP;
    g_fmap[i] = g_numer[n*64 + c] / g_den[n] + bg[c];
}

// ---------------- K7: conv3x3 + bias + PReLU (+ residual) -------------------
__global__ __launch_bounds__(256) void k_conv(
    const float *__restrict__ Kw, const float *__restrict__ bias,
    const float *__restrict__ alpha, float *__restrict__ dout, int sel)
{
    __shared__ float in_s[8*18*22];
    __shared__ float w_s[16*8*9];
    const float *in = sel ? (const float*)g_up1 : (const float*)g_fmap;
    float *out = sel ? dout : (float*)g_up1;
    int tid = threadIdx.x;
    int b = blockIdx.x;
    int x0 = (b % 6) * 16, y0 = ((b / 6) % 6) * 16, ocb = (b / 36) * 16;
    int oc = tid >> 4, g = tid & 15;
    ull acc2[8];
#pragma unroll
    for (int m = 0; m < 8; ++m) acc2[m] = 0ull;
    for (int ic0 = 0; ic0 < 64; ic0 += 8) {
        __syncthreads();
        for (int i = tid; i < 2592; i += 256) {
            int ii = i / 324, rem = i % 324, yy = rem / 18, xx = rem % 18;
            int y = y0 + yy - 1, x = x0 + xx - 1;
            float v = (y >= 0 && y < 96 && x >= 0 && x < 96) ? in[(ic0+ii)*NP + y*96 + x] : 0.f;
            in_s[ii*396 + yy*22 + xx] = v;
        }
        for (int i = tid; i < 1152; i += 256) {
            int o = i / 72, rem = i % 72;
            w_s[i] = Kw[(ocb + o)*576 + ic0*9 + rem];
        }
        __syncthreads();
#pragma unroll
        for (int ic = 0; ic < 8; ++ic) {
#pragma unroll
            for (int dy = 0; dy < 3; ++dy) {
                const float *row = &in_s[ic*396 + (g + dy)*22];
                ull P[9];
#pragma unroll
                for (int m = 0; m < 9; ++m) P[m] = *(const ull*)&row[2*m];
                ull O[8];
#pragma unroll
                for (int m = 0; m < 8; ++m) {
                    float lo, hi, lo2, hi2;
                    upk2(P[m], lo, hi); upk2(P[m+1], lo2, hi2);
                    O[m] = pk2(hi, lo2);
                }
                const float *wr = &w_s[oc*72 + ic*9 + dy*3];
                ull w0 = dup2(wr[0]);
                ull w1 = dup2(wr[1]);
                ull w2 = dup2(wr[2]);
#pragma unroll
                for (int m = 0; m < 8; ++m) {
                    acc2[m] = fma2(w0, P[m],   acc2[m]);
                    acc2[m] = fma2(w1, O[m],   acc2[m]);
                    acc2[m] = fma2(w2, P[m+1], acc2[m]);
                }
            }
        }
    }
    float bv = bias[ocb + oc], av = alpha[0];
    int ocg = ocb + oc;
#pragma unroll
    for (int m = 0; m < 8; ++m) {
        float v0, v1; upk2(acc2[m], v0, v1);
        v0 += bv; v1 += bv;
        v0 = v0 >= 0.f ? v0 : av * v0;
        v1 = v1 >= 0.f ? v1 : av * v1;
        int o = ocg*NP + (y0 + g)*96 + x0 + 2*m;
        if (sel) { v0 += g_hsi_up[o]; v1 += g_hsi_up[o+1]; }
        out[o] = v0; out[o+1] = v1;
    }
}

// ---------------------------------------------------------------------------
extern "C" void kernel_launch(void* const* d_in, const int* in_sizes, int n_in,
                              void* d_out, int out_size)
{
    const float *msi = (const float*)d_in[0];
    const float *hsi = (const float*)d_in[1];
    const float *W1a = (const float*)d_in[2],  *b1a = (const float*)d_in[3],  *a1a = (const float*)d_in[4];
    const float *W1b = (const float*)d_in[5],  *b1b = (const float*)d_in[6],  *a1b = (const float*)d_in[7];
    const float *W2a = (const float*)d_in[8],  *b2a = (const float*)d_in[9],  *a2a = (const float*)d_in[10];
    const float *W2b = (const float*)d_in[11], *b2b = (const float*)d_in[12], *a2b = (const float*)d_in[13];
    const float *Wg  = (const float*)d_in[14];
    const float *al  = (const float*)d_in[15], *ar = (const float*)d_in[16], *bg = (const float*)d_in[17];
    const float *Ku1 = (const float*)d_in[18], *bu1 = (const float*)d_in[19], *au1 = (const float*)d_in[20];
    const float *Ku2 = (const float*)d_in[21], *bu2 = (const float*)d_in[22], *au2 = (const float*)d_in[23];
    float *out = (float*)d_out;

    k_bicubic<<<2304, 256>>>(hsi);
    k_embed<<<576, 256>>>(msi, 0, W1a, b1a, a1a, W1b, b1b, a1b);   // hsi branch
    k_embed<<<576, 256>>>(msi, 1, W2a, b2a, a2a, W2b, b2b, a2b);   // msi branch
    k_sim<<<288, 256>>>();
    k_topk_merge<<<36, 256>>>();
    k_z<<<576, 256>>>(Wg);
    k_elr<<<1152, 256>>>(al, ar);
    k_gat_init<<<2304, 256>>>();
    k_gat_max<<<216, 256>>>();
    k_gat_acc<<<6912, 256>>>();
    k_gat_fin<<<2304, 256>>>(bg);
    k_conv<<<144, 256>>>(Ku1, bu1, au1, out, 0);
    k_conv<<<144, 256>>>(Ku2, bu2, au2, out, 1);
}